// round 1
// baseline (speedup 1.0000x reference)
#include <cuda_runtime.h>
#include <math.h>

#define T_ 4096
#define B_ 8
#define D_ 512
#define H_ 8
#define BS_ 64
#define NB_ 64
#define DH_ 64
#define M_ (T_*B_)            // 32768 rows
#define EPS 1e-5f

// ---------------- scratch (no cudaMalloc allowed) ----------------
__device__ float g_xc [M_ * D_];      // post conv+BN
__device__ float g_q  [M_ * D_];
__device__ float g_k  [M_ * D_];
__device__ float g_v  [M_ * D_];
__device__ float g_att[M_ * D_];      // attention output (pre O-proj)
__device__ float g_x1 [M_ * D_];      // post LN1
__device__ float g_tmp[M_ * D_];      // O-proj out / MLP out
__device__ float g_h  [M_ * 2 * D_];  // MLP hidden

// ---------------- depthwise conv (k=3, cross-correlation) + residual + BN ----
__global__ void conv_bn_kernel(const float* __restrict__ x,
                               const float* __restrict__ w,
                               const float* __restrict__ gam,
                               const float* __restrict__ bet,
                               const float* __restrict__ mu,
                               const float* __restrict__ var) {
    int idx = blockIdx.x * blockDim.x + threadIdx.x;
    if (idx >= M_ * D_) return;
    int d = idx % D_;
    int t = idx / (B_ * D_);
    float x0 = x[idx];
    float xm = (t > 0)      ? x[idx - B_ * D_] : 0.f;
    float xp = (t < T_ - 1) ? x[idx + B_ * D_] : 0.f;
    float y = w[d * 3 + 0] * xm + w[d * 3 + 1] * x0 + w[d * 3 + 2] * xp + x0;
    y = (y - mu[d]) * rsqrtf(var[d] + EPS) * gam[d] + bet[d];
    g_xc[idx] = y;
}

// ---------------- fp32 SGEMM: C[M,N] = A[M,K] @ B[K,N] + bias, optional GeLU ----
// BM=BN=128, BK=8, 256 threads, 8x8 microtile. M,N,K all multiples of tile dims.
template<bool GELU>
__global__ void __launch_bounds__(256) sgemm_bias(const float* __restrict__ A,
                                                  const float* __restrict__ Bm,
                                                  const float* __restrict__ bias,
                                                  float* __restrict__ C,
                                                  int K, int N) {
    __shared__ float As[8][128];
    __shared__ float Bs[8][128];
    int tid = threadIdx.x;
    int tx = tid & 15, ty = tid >> 4;
    int rowBase = blockIdx.y * 128;
    int colBase = blockIdx.x * 128;

    float acc[8][8];
    #pragma unroll
    for (int i = 0; i < 8; i++)
        #pragma unroll
        for (int j = 0; j < 8; j++) acc[i][j] = 0.f;

    int arow = tid >> 1, acol = (tid & 1) * 4;
    int brow = tid >> 5, bcol = (tid & 31) * 4;
    const float* Aptr = A  + (size_t)(rowBase + arow) * K + acol;
    const float* Bptr = Bm + (size_t)brow * N + colBase + bcol;

    for (int k0 = 0; k0 < K; k0 += 8) {
        float4 av = *(const float4*)(Aptr + k0);
        As[acol + 0][arow] = av.x;
        As[acol + 1][arow] = av.y;
        As[acol + 2][arow] = av.z;
        As[acol + 3][arow] = av.w;
        float4 bv = *(const float4*)(Bptr + (size_t)k0 * N);
        *(float4*)&Bs[brow][bcol] = bv;
        __syncthreads();
        #pragma unroll
        for (int kk = 0; kk < 8; kk++) {
            float a[8], b[8];
            #pragma unroll
            for (int i = 0; i < 8; i++) a[i] = As[kk][ty * 8 + i];
            #pragma unroll
            for (int j = 0; j < 8; j++) b[j] = Bs[kk][tx * 8 + j];
            #pragma unroll
            for (int i = 0; i < 8; i++)
                #pragma unroll
                for (int j = 0; j < 8; j++) acc[i][j] += a[i] * b[j];
        }
        __syncthreads();
    }

    #pragma unroll
    for (int i = 0; i < 8; i++) {
        int row = rowBase + ty * 8 + i;
        #pragma unroll
        for (int j = 0; j < 8; j++) {
            int col = colBase + tx * 8 + j;
            float val = acc[i][j] + bias[col];
            if (GELU) val = 0.5f * val * (1.0f + erff(val * 0.70710678118654752f));
            C[(size_t)row * N + col] = val;
        }
    }
}

// ---------------- bucketed sparse attention ----------------
// One CTA per (b, h, nb). 256 threads. smem: Q[64x65] K->P[128x65] V[128x65].
__global__ void __launch_bounds__(256) attn_kernel(const float* __restrict__ q,
                                                   const float* __restrict__ k,
                                                   const float* __restrict__ v,
                                                   const int* __restrict__ rand_idx,
                                                   const int* __restrict__ t_len,
                                                   float* __restrict__ out) {
    extern __shared__ float sm[];
    float* Qs = sm;                // 64*65
    float* KP = sm + 64 * 65;      // 128*65 (K tile, later reused as P 64x130)
    float* Vs = KP + 128 * 65;     // 128*65

    int tid = threadIdx.x;
    int nb = blockIdx.x % NB_;
    int h  = (blockIdx.x / NB_) % H_;
    int b  = blockIdx.x / (NB_ * H_);
    int rnb  = rand_idx[nb];
    int tlen = t_len[b];

    // --- load Q (64 rows x 64) ---
    for (int idx = tid; idx < 64 * 16; idx += 256) {
        int i = idx >> 4, f = (idx & 15) << 2;
        const float* p = &q[((size_t)(nb * 64 + i) * B_ + b) * D_ + h * DH_ + f];
        float4 val = *(const float4*)p;
        float* dst = &Qs[i * 65 + f];
        dst[0] = val.x; dst[1] = val.y; dst[2] = val.z; dst[3] = val.w;
    }
    // --- load K,V (128 rows: own bucket then random bucket) ---
    for (int idx = tid; idx < 128 * 16; idx += 256) {
        int i = idx >> 4, f = (idx & 15) << 2;
        int t = (i < 64) ? nb * 64 + i : rnb * 64 + (i - 64);
        size_t off = ((size_t)t * B_ + b) * D_ + h * DH_ + f;
        float4 kv = *(const float4*)&k[off];
        float* kd = &KP[i * 65 + f];
        kd[0] = kv.x; kd[1] = kv.y; kd[2] = kv.z; kd[3] = kv.w;
        float4 vv = *(const float4*)&v[off];
        float* vd = &Vs[i * 65 + f];
        vd[0] = vv.x; vd[1] = vv.y; vd[2] = vv.z; vd[3] = vv.w;
    }
    __syncthreads();

    // --- scores: thread owns query row qi = tid/4, key cols kj = kc + 4*j ---
    int qi = tid >> 2, kc = tid & 3;
    float s[32];
    #pragma unroll
    for (int j = 0; j < 32; j++) s[j] = 0.f;
    for (int d = 0; d < 64; d++) {
        float qv = Qs[qi * 65 + d];
        #pragma unroll
        for (int j = 0; j < 32; j++)
            s[j] += qv * KP[(4 * j + kc) * 65 + d];
    }
    // scale + mask + row max
    float mx = -INFINITY;
    #pragma unroll
    for (int j = 0; j < 32; j++) {
        int kj  = 4 * j + kc;
        int pos = (kj < 64) ? nb * 64 + kj : rnb * 64 + (kj - 64);
        float sc = s[j] * 0.125f;
        if (pos >= tlen) sc = -1e9f;
        s[j] = sc;
        mx = fmaxf(mx, sc);
    }
    mx = fmaxf(mx, __shfl_xor_sync(0xffffffffu, mx, 1));
    mx = fmaxf(mx, __shfl_xor_sync(0xffffffffu, mx, 2));
    float sum = 0.f;
    #pragma unroll
    for (int j = 0; j < 32; j++) { s[j] = __expf(s[j] - mx); sum += s[j]; }
    sum += __shfl_xor_sync(0xffffffffu, sum, 1);
    sum += __shfl_xor_sync(0xffffffffu, sum, 2);
    float inv = 1.f / sum;

    __syncthreads();   // all K reads complete before overwriting with P
    #pragma unroll
    for (int j = 0; j < 32; j++) KP[qi * 130 + 4 * j + kc] = s[j] * inv;
    __syncthreads();

    // --- O = P @ V: thread owns row qi, cols dh = kc + 4*jj ---
    float acc[16];
    #pragma unroll
    for (int jj = 0; jj < 16; jj++) acc[jj] = 0.f;
    for (int kj = 0; kj < 128; kj++) {
        float p = KP[qi * 130 + kj];
        #pragma unroll
        for (int jj = 0; jj < 16; jj++)
            acc[jj] += p * Vs[kj * 65 + kc + 4 * jj];
    }
    size_t base = ((size_t)(nb * 64 + qi) * B_ + b) * D_ + h * DH_;
    #pragma unroll
    for (int jj = 0; jj < 16; jj++) out[base + kc + 4 * jj] = acc[jj];
}

// ---------------- residual + LayerNorm (population var) ----------------
__global__ void __launch_bounds__(128) ln_res_kernel(const float* __restrict__ a,
                                                     const float* __restrict__ r,
                                                     const float* __restrict__ gam,
                                                     const float* __restrict__ bet,
                                                     float* __restrict__ out) {
    int row = blockIdx.x;
    int tid = threadIdx.x;
    const float* ap = a + (size_t)row * D_;
    const float* rp = r + (size_t)row * D_;
    float vals[4];
    float s = 0.f, sq = 0.f;
    #pragma unroll
    for (int i = 0; i < 4; i++) {
        int c = tid + i * 128;
        float xv = ap[c] + rp[c];
        vals[i] = xv; s += xv; sq += xv * xv;
    }
    #pragma unroll
    for (int o = 16; o; o >>= 1) {
        s  += __shfl_xor_sync(0xffffffffu, s,  o);
        sq += __shfl_xor_sync(0xffffffffu, sq, o);
    }
    __shared__ float ss[4], ssq[4];
    int w = tid >> 5, l = tid & 31;
    if (l == 0) { ss[w] = s; ssq[w] = sq; }
    __syncthreads();
    s  = ss[0]  + ss[1]  + ss[2]  + ss[3];
    sq = ssq[0] + ssq[1] + ssq[2] + ssq[3];
    float mean = s * (1.f / D_);
    float var  = sq * (1.f / D_) - mean * mean;
    float rstd = rsqrtf(var + EPS);
    #pragma unroll
    for (int i = 0; i < 4; i++) {
        int c = tid + i * 128;
        out[(size_t)row * D_ + c] = (vals[i] - mean) * rstd * gam[c] + bet[c];
    }
}

// ---------------- launch ----------------
extern "C" void kernel_launch(void* const* d_in, const int* in_sizes, int n_in,
                              void* d_out, int out_size) {
    const float* x        = (const float*)d_in[0];
    const int*   t_length = (const int*)  d_in[1];
    const int*   rand_idx = (const int*)  d_in[2];
    const float* conv_w   = (const float*)d_in[3];
    const float* bn_g     = (const float*)d_in[4];
    const float* bn_b     = (const float*)d_in[5];
    const float* bn_m     = (const float*)d_in[6];
    const float* bn_v     = (const float*)d_in[7];
    const float* wq = (const float*)d_in[8],  *bq = (const float*)d_in[9];
    const float* wk = (const float*)d_in[10], *bk = (const float*)d_in[11];
    const float* wv = (const float*)d_in[12], *bv = (const float*)d_in[13];
    const float* wo = (const float*)d_in[14], *bo = (const float*)d_in[15];
    const float* ln1_g = (const float*)d_in[16], *ln1_b = (const float*)d_in[17];
    const float* w1 = (const float*)d_in[18], *b1 = (const float*)d_in[19];
    const float* w2 = (const float*)d_in[20], *b2 = (const float*)d_in[21];
    const float* ln2_g = (const float*)d_in[22], *ln2_b = (const float*)d_in[23];
    float* out = (float*)d_out;

    float *xc, *qb, *kb, *vb, *att, *x1, *tmp, *hb;
    cudaGetSymbolAddress((void**)&xc,  g_xc);
    cudaGetSymbolAddress((void**)&qb,  g_q);
    cudaGetSymbolAddress((void**)&kb,  g_k);
    cudaGetSymbolAddress((void**)&vb,  g_v);
    cudaGetSymbolAddress((void**)&att, g_att);
    cudaGetSymbolAddress((void**)&x1,  g_x1);
    cudaGetSymbolAddress((void**)&tmp, g_tmp);
    cudaGetSymbolAddress((void**)&hb,  g_h);

    // 1. conv + residual + BN
    conv_bn_kernel<<<(M_ * D_) / 256, 256>>>(x, conv_w, bn_g, bn_b, bn_m, bn_v);

    // 2. QKV projections
    dim3 gD(D_ / 128, M_ / 128);
    sgemm_bias<false><<<gD, 256>>>(xc, wq, bq, qb, D_, D_);
    sgemm_bias<false><<<gD, 256>>>(xc, wk, bk, kb, D_, D_);
    sgemm_bias<false><<<gD, 256>>>(xc, wv, bv, vb, D_, D_);

    // 3. bucketed sparse attention
    cudaFuncSetAttribute(attn_kernel, cudaFuncAttributeMaxDynamicSharedMemorySize, 83200);
    attn_kernel<<<B_ * H_ * NB_, 256, 83200>>>(qb, kb, vb, rand_idx, t_length, att);

    // 4. O projection, residual + LN1
    sgemm_bias<false><<<gD, 256>>>(att, wo, bo, tmp, D_, D_);
    ln_res_kernel<<<M_, 128>>>(tmp, xc, ln1_g, ln1_b, x1);

    // 5. MLP
    dim3 gH((2 * D_) / 128, M_ / 128);
    sgemm_bias<true><<<gH, 256>>>(x1, w1, b1, hb, D_, 2 * D_);
    sgemm_bias<false><<<gD, 256>>>(hb, w2, b2, tmp, 2 * D_, D_);

    // 6. residual + LN2 -> output
    ln_res_kernel<<<M_, 128>>>(tmp, x1, ln2_g, ln2_b, out);
}

// round 8
// speedup vs baseline: 2.1245x; 2.1245x over previous
#include <cuda_runtime.h>
#include <cuda_bf16.h>
#include <math.h>
#include <stdint.h>

#define T_ 4096
#define B_ 8
#define D_ 512
#define H_ 8
#define BS_ 64
#define NB_ 64
#define DH_ 64
#define M_ (T_*B_)            // 32768 rows
#define EPS 1e-5f

// ---------------- scratch (no cudaMalloc allowed) ----------------
__device__ float g_xc [M_ * D_];      // post conv+BN
__device__ float g_q  [M_ * D_];
__device__ float g_k  [M_ * D_];
__device__ float g_v  [M_ * D_];
__device__ float g_att[M_ * D_];      // attention output (pre O-proj)
__device__ float g_x1 [M_ * D_];      // post LN1
__device__ float g_tmp[M_ * D_];      // O-proj out / MLP out
__device__ float g_h  [M_ * 2 * D_];  // MLP hidden (post GeLU)

// bf16 split activation buffers (reused across GEMMs)
__device__ __nv_bfloat16 g_ah[M_ * 2 * D_];
__device__ __nv_bfloat16 g_al[M_ * 2 * D_];
// bf16 split transposed weights ([N,K] layout, K contiguous)
__device__ __nv_bfloat16 g_wqh[D_*D_],  g_wql[D_*D_];
__device__ __nv_bfloat16 g_wkh[D_*D_],  g_wkl[D_*D_];
__device__ __nv_bfloat16 g_wvh[D_*D_],  g_wvl[D_*D_];
__device__ __nv_bfloat16 g_woh[D_*D_],  g_wol[D_*D_];
__device__ __nv_bfloat16 g_w1h[2*D_*D_], g_w1l[2*D_*D_];
__device__ __nv_bfloat16 g_w2h[2*D_*D_], g_w2l[2*D_*D_];

// ================= base-ISA helpers (compile at .target sm_103) ==========
__device__ __forceinline__ uint32_t smem_u32(const void* p) {
    uint32_t a;
    asm("{ .reg .u64 t; cvta.to.shared.u64 t, %1; cvt.u32.u64 %0, t; }"
        : "=r"(a) : "l"(p));
    return a;
}
#define CP_ASYNC16(dst, src) \
    asm volatile("cp.async.cg.shared.global [%0], [%1], 16;" \
        :: "r"(dst), "l"(src))
#define CP_COMMIT() asm volatile("cp.async.commit_group;" ::: "memory")
#define CP_WAIT(n)  asm volatile("cp.async.wait_group %0;" :: "n"(n) : "memory")

__device__ __forceinline__ void ldm_x4(uint32_t* r, uint32_t addr) {
    asm volatile("ldmatrix.sync.aligned.m8n8.x4.shared.b16 {%0,%1,%2,%3}, [%4];"
        : "=r"(r[0]), "=r"(r[1]), "=r"(r[2]), "=r"(r[3]) : "r"(addr));
}
__device__ __forceinline__ void ldm_x2(uint32_t* r, uint32_t addr) {
    asm volatile("ldmatrix.sync.aligned.m8n8.x2.shared.b16 {%0,%1}, [%2];"
        : "=r"(r[0]), "=r"(r[1]) : "r"(addr));
}
#define MMA_BF16(c, a, b) \
    asm volatile("mma.sync.aligned.m16n8k16.row.col.f32.bf16.bf16.f32 " \
        "{%0,%1,%2,%3}, {%4,%5,%6,%7}, {%8,%9}, {%0,%1,%2,%3};" \
        : "+f"((c)[0]), "+f"((c)[1]), "+f"((c)[2]), "+f"((c)[3]) \
        : "r"((a)[0]), "r"((a)[1]), "r"((a)[2]), "r"((a)[3]), \
          "r"((b)[0]), "r"((b)[1]))

// ================= conversion kernels =================
// fp32 -> bf16 hi + bf16 lo (split)
__global__ void __launch_bounds__(256) split_kernel(const float* __restrict__ x,
                                                    __nv_bfloat16* __restrict__ hi,
                                                    __nv_bfloat16* __restrict__ lo,
                                                    int n) {
    int i = (blockIdx.x * 256 + threadIdx.x) * 4;
    if (i >= n) return;
    float4 v = *(const float4*)(x + i);
    __nv_bfloat16 h0 = __float2bfloat16_rn(v.x);
    __nv_bfloat16 h1 = __float2bfloat16_rn(v.y);
    __nv_bfloat16 h2 = __float2bfloat16_rn(v.z);
    __nv_bfloat16 h3 = __float2bfloat16_rn(v.w);
    __nv_bfloat16 l0 = __float2bfloat16_rn(v.x - __bfloat162float(h0));
    __nv_bfloat16 l1 = __float2bfloat16_rn(v.y - __bfloat162float(h1));
    __nv_bfloat16 l2 = __float2bfloat16_rn(v.z - __bfloat162float(h2));
    __nv_bfloat16 l3 = __float2bfloat16_rn(v.w - __bfloat162float(h3));
    *(__nv_bfloat162*)(hi + i)     = __nv_bfloat162(h0, h1);
    *(__nv_bfloat162*)(hi + i + 2) = __nv_bfloat162(h2, h3);
    *(__nv_bfloat162*)(lo + i)     = __nv_bfloat162(l0, l1);
    *(__nv_bfloat162*)(lo + i + 2) = __nv_bfloat162(l2, l3);
}

// weight [K,N] fp32 -> [N,K] bf16 hi/lo (transpose + split)
__global__ void __launch_bounds__(256) wsplit_t(const float* __restrict__ w,
                                                __nv_bfloat16* __restrict__ hi,
                                                __nv_bfloat16* __restrict__ lo,
                                                int K, int N) {
    __shared__ float t[32][33];
    int n0 = blockIdx.x * 32, k0 = blockIdx.y * 32;
    int tx = threadIdx.x & 31, ty = threadIdx.x >> 5;  // 32x8
    #pragma unroll
    for (int i = 0; i < 32; i += 8)
        t[ty + i][tx] = w[(size_t)(k0 + ty + i) * N + n0 + tx];
    __syncthreads();
    #pragma unroll
    for (int i = 0; i < 32; i += 8) {
        float v = t[tx][ty + i];     // k_local = tx, n_local = ty+i
        __nv_bfloat16 h = __float2bfloat16_rn(v);
        __nv_bfloat16 l = __float2bfloat16_rn(v - __bfloat162float(h));
        size_t off = (size_t)(n0 + ty + i) * K + k0 + tx;
        hi[off] = h; lo[off] = l;
    }
}

// ================= mma.sync split-bf16 GEMM =================
// C[M,N] = A[M,K] @ W[K,N] + bias (3-term split), W pre-transposed to [N,K].
// CTA tile 128x128, BK=64 per stage, 2 cp.async stages, 8 warps @ 64x32.
// SMEM row stride 72 bf16 (144 B) -> conflict-free ldmatrix.
#define STG_  73728          // 4 matrices * 128 rows * 144 B
#define MATB_ 18432          // one matrix: 128 * 144

template<int K, bool GELU>
__global__ void __launch_bounds__(256) gemm_mma(
    const __nv_bfloat16* __restrict__ Ah, const __nv_bfloat16* __restrict__ Al,
    const __nv_bfloat16* __restrict__ Bh, const __nv_bfloat16* __restrict__ Bl,
    const float* __restrict__ bias, float* __restrict__ C, int N)
{
    extern __shared__ char smem[];
    uint32_t sb = smem_u32(smem);
    int tid = threadIdx.x, wid = tid >> 5, lane = tid & 31;
    int wrow = wid >> 2, wcol = wid & 3;            // 2 x 4 warp grid
    int rowBase = blockIdx.y * 128, colBase = blockIdx.x * 128;

    float acc[4][4][4];
    #pragma unroll
    for (int mt = 0; mt < 4; mt++)
        #pragma unroll
        for (int nt = 0; nt < 4; nt++)
            #pragma unroll
            for (int j = 0; j < 4; j++) acc[mt][nt][j] = 0.f;

    const __nv_bfloat16* gsrc[4] = {Ah, Al, Bh, Bl};

    auto load_stage = [&](int s, int chunk) {
        int k0 = chunk * 64;
        #pragma unroll
        for (int it = 0; it < 16; it++) {
            int u = it * 256 + tid;
            int mat = u >> 10;                       // constant per it
            int rem = u & 1023, r = rem >> 3, c = rem & 7;
            int rb = (mat < 2) ? rowBase : colBase;
            const void* src = gsrc[mat] + (size_t)(rb + r) * K + k0 + c * 8;
            uint32_t dst = sb + s * STG_ + mat * MATB_ + r * 144 + c * 16;
            CP_ASYNC16(dst, src);
        }
    };

    auto compute = [&](int s) {
        uint32_t aH = sb + s * STG_ + (wrow * 64 + (lane & 15)) * 144 + (lane >> 4) * 16;
        uint32_t aL = aH + MATB_;
        uint32_t bH = sb + s * STG_ + 2 * MATB_
                    + (wcol * 32 + (lane & 7)) * 144 + ((lane >> 3) & 1) * 16;
        uint32_t bL = bH + MATB_;
        #pragma unroll
        for (int ks = 0; ks < 4; ks++) {
            uint32_t ah[4][4], al[4][4];
            #pragma unroll
            for (int mt = 0; mt < 4; mt++) {
                ldm_x4(ah[mt], aH + mt * (16 * 144) + ks * 32);
                ldm_x4(al[mt], aL + mt * (16 * 144) + ks * 32);
            }
            #pragma unroll
            for (int nt = 0; nt < 4; nt++) {
                uint32_t bh[2], bl[2];
                ldm_x2(bh, bH + nt * (8 * 144) + ks * 32);
                ldm_x2(bl, bL + nt * (8 * 144) + ks * 32);
                #pragma unroll
                for (int mt = 0; mt < 4; mt++) {
                    MMA_BF16(acc[mt][nt], ah[mt], bh);
                    MMA_BF16(acc[mt][nt], ah[mt], bl);
                    MMA_BF16(acc[mt][nt], al[mt], bh);
                }
            }
        }
    };

    constexpr int NCH = K / 64;
    load_stage(0, 0); CP_COMMIT();
    for (int i = 0; i < NCH; i++) {
        if (i + 1 < NCH) { load_stage((i + 1) & 1, i + 1); CP_COMMIT(); CP_WAIT(1); }
        else             { CP_WAIT(0); }
        __syncthreads();
        compute(i & 1);
        __syncthreads();
    }

    // ---- epilogue ----
    #pragma unroll
    for (int mt = 0; mt < 4; mt++) {
        int row = rowBase + wrow * 64 + mt * 16 + (lane >> 2);
        #pragma unroll
        for (int nt = 0; nt < 4; nt++) {
            int col = colBase + wcol * 32 + nt * 8 + (lane & 3) * 2;
            float b0 = bias[col], b1 = bias[col + 1];
            float v0 = acc[mt][nt][0] + b0, v1 = acc[mt][nt][1] + b1;
            float v2 = acc[mt][nt][2] + b0, v3 = acc[mt][nt][3] + b1;
            if (GELU) {
                v0 = 0.5f * v0 * (1.0f + erff(v0 * 0.70710678118654752f));
                v1 = 0.5f * v1 * (1.0f + erff(v1 * 0.70710678118654752f));
                v2 = 0.5f * v2 * (1.0f + erff(v2 * 0.70710678118654752f));
                v3 = 0.5f * v3 * (1.0f + erff(v3 * 0.70710678118654752f));
            }
            float2 o01 = make_float2(v0, v1);
            float2 o23 = make_float2(v2, v3);
            *(float2*)&C[(size_t)row * N + col]       = o01;
            *(float2*)&C[(size_t)(row + 8) * N + col] = o23;
        }
    }
}

// ---------------- depthwise conv (k=3) + residual + BN ----------------
__global__ void conv_bn_kernel(const float* __restrict__ x,
                               const float* __restrict__ w,
                               const float* __restrict__ gam,
                               const float* __restrict__ bet,
                               const float* __restrict__ mu,
                               const float* __restrict__ var) {
    int idx = blockIdx.x * blockDim.x + threadIdx.x;
    if (idx >= M_ * D_) return;
    int d = idx % D_;
    int t = idx / (B_ * D_);
    float x0 = x[idx];
    float xm = (t > 0)      ? x[idx - B_ * D_] : 0.f;
    float xp = (t < T_ - 1) ? x[idx + B_ * D_] : 0.f;
    float y = w[d * 3 + 0] * xm + w[d * 3 + 1] * x0 + w[d * 3 + 2] * xp + x0;
    y = (y - mu[d]) * rsqrtf(var[d] + EPS) * gam[d] + bet[d];
    g_xc[idx] = y;
}

// ---------------- bucketed sparse attention ----------------
__global__ void __launch_bounds__(256) attn_kernel(const float* __restrict__ q,
                                                   const float* __restrict__ k,
                                                   const float* __restrict__ v,
                                                   const int* __restrict__ rand_idx,
                                                   const int* __restrict__ t_len,
                                                   float* __restrict__ out) {
    extern __shared__ float sm[];
    float* Qs = sm;                // 64*65
    float* KP = sm + 64 * 65;      // 128*65 (K tile, later reused as P 64x130)
    float* Vs = KP + 128 * 65;     // 128*65

    int tid = threadIdx.x;
    int nb = blockIdx.x % NB_;
    int h  = (blockIdx.x / NB_) % H_;
    int b  = blockIdx.x / (NB_ * H_);
    int rnb  = rand_idx[nb];
    int tlen = t_len[b];

    for (int idx = tid; idx < 64 * 16; idx += 256) {
        int i = idx >> 4, f = (idx & 15) << 2;
        const float* p = &q[((size_t)(nb * 64 + i) * B_ + b) * D_ + h * DH_ + f];
        float4 val = *(const float4*)p;
        float* dst = &Qs[i * 65 + f];
        dst[0] = val.x; dst[1] = val.y; dst[2] = val.z; dst[3] = val.w;
    }
    for (int idx = tid; idx < 128 * 16; idx += 256) {
        int i = idx >> 4, f = (idx & 15) << 2;
        int t = (i < 64) ? nb * 64 + i : rnb * 64 + (i - 64);
        size_t off = ((size_t)t * B_ + b) * D_ + h * DH_ + f;
        float4 kv = *(const float4*)&k[off];
        float* kd = &KP[i * 65 + f];
        kd[0] = kv.x; kd[1] = kv.y; kd[2] = kv.z; kd[3] = kv.w;
        float4 vv = *(const float4*)&v[off];
        float* vd = &Vs[i * 65 + f];
        vd[0] = vv.x; vd[1] = vv.y; vd[2] = vv.z; vd[3] = vv.w;
    }
    __syncthreads();

    int qi = tid >> 2, kc = tid & 3;
    float s[32];
    #pragma unroll
    for (int j = 0; j < 32; j++) s[j] = 0.f;
    for (int d = 0; d < 64; d++) {
        float qv = Qs[qi * 65 + d];
        #pragma unroll
        for (int j = 0; j < 32; j++)
            s[j] += qv * KP[(4 * j + kc) * 65 + d];
    }
    float mx = -INFINITY;
    #pragma unroll
    for (int j = 0; j < 32; j++) {
        int kj  = 4 * j + kc;
        int pos = (kj < 64) ? nb * 64 + kj : rnb * 64 + (kj - 64);
        float sc = s[j] * 0.125f;
        if (pos >= tlen) sc = -1e9f;
        s[j] = sc;
        mx = fmaxf(mx, sc);
    }
    mx = fmaxf(mx, __shfl_xor_sync(0xffffffffu, mx, 1));
    mx = fmaxf(mx, __shfl_xor_sync(0xffffffffu, mx, 2));
    float sum = 0.f;
    #pragma unroll
    for (int j = 0; j < 32; j++) { s[j] = __expf(s[j] - mx); sum += s[j]; }
    sum += __shfl_xor_sync(0xffffffffu, sum, 1);
    sum += __shfl_xor_sync(0xffffffffu, sum, 2);
    float inv = 1.f / sum;

    __syncthreads();
    #pragma unroll
    for (int j = 0; j < 32; j++) KP[qi * 130 + 4 * j + kc] = s[j] * inv;
    __syncthreads();

    float acc[16];
    #pragma unroll
    for (int jj = 0; jj < 16; jj++) acc[jj] = 0.f;
    for (int kj = 0; kj < 128; kj++) {
        float p = KP[qi * 130 + kj];
        #pragma unroll
        for (int jj = 0; jj < 16; jj++)
            acc[jj] += p * Vs[kj * 65 + kc + 4 * jj];
    }
    size_t base = ((size_t)(nb * 64 + qi) * B_ + b) * D_ + h * DH_;
    #pragma unroll
    for (int jj = 0; jj < 16; jj++) out[base + kc + 4 * jj] = acc[jj];
}

// ---------------- residual + LayerNorm ----------------
__global__ void __launch_bounds__(128) ln_res_kernel(const float* __restrict__ a,
                                                     const float* __restrict__ r,
                                                     const float* __restrict__ gam,
                                                     const float* __restrict__ bet,
                                                     float* __restrict__ out) {
    int row = blockIdx.x;
    int tid = threadIdx.x;
    const float* ap = a + (size_t)row * D_;
    const float* rp = r + (size_t)row * D_;
    float vals[4];
    float s = 0.f, sq = 0.f;
    #pragma unroll
    for (int i = 0; i < 4; i++) {
        int c = tid + i * 128;
        float xv = ap[c] + rp[c];
        vals[i] = xv; s += xv; sq += xv * xv;
    }
    #pragma unroll
    for (int o = 16; o; o >>= 1) {
        s  += __shfl_xor_sync(0xffffffffu, s,  o);
        sq += __shfl_xor_sync(0xffffffffu, sq, o);
    }
    __shared__ float ss[4], ssq[4];
    int w = tid >> 5, l = tid & 31;
    if (l == 0) { ss[w] = s; ssq[w] = sq; }
    __syncthreads();
    s  = ss[0]  + ss[1]  + ss[2]  + ss[3];
    sq = ssq[0] + ssq[1] + ssq[2] + ssq[3];
    float mean = s * (1.f / D_);
    float var  = sq * (1.f / D_) - mean * mean;
    float rstd = rsqrtf(var + EPS);
    #pragma unroll
    for (int i = 0; i < 4; i++) {
        int c = tid + i * 128;
        out[(size_t)row * D_ + c] = (vals[i] - mean) * rstd * gam[c] + bet[c];
    }
}

// ---------------- launch ----------------
extern "C" void kernel_launch(void* const* d_in, const int* in_sizes, int n_in,
                              void* d_out, int out_size) {
    const float* x        = (const float*)d_in[0];
    const int*   t_length = (const int*)  d_in[1];
    const int*   rand_idx = (const int*)  d_in[2];
    const float* conv_w   = (const float*)d_in[3];
    const float* bn_g     = (const float*)d_in[4];
    const float* bn_b     = (const float*)d_in[5];
    const float* bn_m     = (const float*)d_in[6];
    const float* bn_v     = (const float*)d_in[7];
    const float* wq = (const float*)d_in[8],  *bq = (const float*)d_in[9];
    const float* wk = (const float*)d_in[10], *bk = (const float*)d_in[11];
    const float* wv = (const float*)d_in[12], *bv = (const float*)d_in[13];
    const float* wo = (const float*)d_in[14], *bo = (const float*)d_in[15];
    const float* ln1_g = (const float*)d_in[16], *ln1_b = (const float*)d_in[17];
    const float* w1 = (const float*)d_in[18], *b1 = (const float*)d_in[19];
    const float* w2 = (const float*)d_in[20], *b2 = (const float*)d_in[21];
    const float* ln2_g = (const float*)d_in[22], *ln2_b = (const float*)d_in[23];
    float* out = (float*)d_out;

    float *xc, *qb, *kb, *vb, *att, *x1, *tmp, *hb;
    cudaGetSymbolAddress((void**)&xc,  g_xc);
    cudaGetSymbolAddress((void**)&qb,  g_q);
    cudaGetSymbolAddress((void**)&kb,  g_k);
    cudaGetSymbolAddress((void**)&vb,  g_v);
    cudaGetSymbolAddress((void**)&att, g_att);
    cudaGetSymbolAddress((void**)&x1,  g_x1);
    cudaGetSymbolAddress((void**)&tmp, g_tmp);
    cudaGetSymbolAddress((void**)&hb,  g_h);

    __nv_bfloat16 *ah, *al;
    __nv_bfloat16 *wqh,*wql,*wkh,*wkl,*wvh,*wvl,*woh,*wol,*w1h,*w1l,*w2h,*w2l;
    cudaGetSymbolAddress((void**)&ah,  g_ah);
    cudaGetSymbolAddress((void**)&al,  g_al);
    cudaGetSymbolAddress((void**)&wqh, g_wqh); cudaGetSymbolAddress((void**)&wql, g_wql);
    cudaGetSymbolAddress((void**)&wkh, g_wkh); cudaGetSymbolAddress((void**)&wkl, g_wkl);
    cudaGetSymbolAddress((void**)&wvh, g_wvh); cudaGetSymbolAddress((void**)&wvl, g_wvl);
    cudaGetSymbolAddress((void**)&woh, g_woh); cudaGetSymbolAddress((void**)&wol, g_wol);
    cudaGetSymbolAddress((void**)&w1h, g_w1h); cudaGetSymbolAddress((void**)&w1l, g_w1l);
    cudaGetSymbolAddress((void**)&w2h, g_w2h); cudaGetSymbolAddress((void**)&w2l, g_w2l);

    const int GEMM_SMEM = 2 * STG_;   // 147456
    cudaFuncSetAttribute(gemm_mma<512, false>,  cudaFuncAttributeMaxDynamicSharedMemorySize, GEMM_SMEM);
    cudaFuncSetAttribute(gemm_mma<512, true>,   cudaFuncAttributeMaxDynamicSharedMemorySize, GEMM_SMEM);
    cudaFuncSetAttribute(gemm_mma<1024, false>, cudaFuncAttributeMaxDynamicSharedMemorySize, GEMM_SMEM);
    cudaFuncSetAttribute(attn_kernel, cudaFuncAttributeMaxDynamicSharedMemorySize, 83200);

    // 0. split-transpose all weights (small)
    dim3 wt(256);
    wsplit_t<<<dim3(D_/32, D_/32),       wt>>>(wq, wqh, wql, D_, D_);
    wsplit_t<<<dim3(D_/32, D_/32),       wt>>>(wk, wkh, wkl, D_, D_);
    wsplit_t<<<dim3(D_/32, D_/32),       wt>>>(wv, wvh, wvl, D_, D_);
    wsplit_t<<<dim3(D_/32, D_/32),       wt>>>(wo, woh, wol, D_, D_);
    wsplit_t<<<dim3((2*D_)/32, D_/32),   wt>>>(w1, w1h, w1l, D_, 2*D_);
    wsplit_t<<<dim3(D_/32, (2*D_)/32),   wt>>>(w2, w2h, w2l, 2*D_, D_);

    // 1. conv + residual + BN
    conv_bn_kernel<<<(M_ * D_) / 256, 256>>>(x, conv_w, bn_g, bn_b, bn_m, bn_v);

    // 2. QKV projections (split xc once, 3 GEMMs)
    split_kernel<<<(M_ * D_) / 1024, 256>>>(xc, ah, al, M_ * D_);
    dim3 gD(D_ / 128, M_ / 128);
    gemm_mma<512, false><<<gD, 256, GEMM_SMEM>>>(ah, al, wqh, wql, bq, qb, D_);
    gemm_mma<512, false><<<gD, 256, GEMM_SMEM>>>(ah, al, wkh, wkl, bk, kb, D_);
    gemm_mma<512, false><<<gD, 256, GEMM_SMEM>>>(ah, al, wvh, wvl, bv, vb, D_);

    // 3. bucketed sparse attention
    attn_kernel<<<B_ * H_ * NB_, 256, 83200>>>(qb, kb, vb, rand_idx, t_length, att);

    // 4. O projection, residual + LN1
    split_kernel<<<(M_ * D_) / 1024, 256>>>(att, ah, al, M_ * D_);
    gemm_mma<512, false><<<gD, 256, GEMM_SMEM>>>(ah, al, woh, wol, bo, tmp, D_);
    ln_res_kernel<<<M_, 128>>>(tmp, xc, ln1_g, ln1_b, x1);

    // 5. MLP
    split_kernel<<<(M_ * D_) / 1024, 256>>>(x1, ah, al, M_ * D_);
    dim3 gH((2 * D_) / 128, M_ / 128);
    gemm_mma<512, true><<<gH, 256, GEMM_SMEM>>>(ah, al, w1h, w1l, b1, hb, 2 * D_);
    split_kernel<<<(M_ * 2 * D_) / 1024, 256>>>(hb, ah, al, M_ * 2 * D_);
    gemm_mma<1024, false><<<gD, 256, GEMM_SMEM>>>(ah, al, w2h, w2l, b2, tmp, D_);

    // 6. residual + LN2 -> output
    ln_res_kernel<<<M_, 128>>>(tmp, x1, ln2_g, ln2_b, out);
}